// round 5
// baseline (speedup 1.0000x reference)
#include <cuda_runtime.h>
#include <cuda_bf16.h>
#include <cstdint>

#define B_DIM 16
#define T_DIM 1024
#define V_DIM 128
#define N_ROWS (B_DIM * T_DIM)                  // 16384
#define WARPS_PER_BLOCK 8
#define THREADS_PER_BLOCK (WARPS_PER_BLOCK * 32)
#define ROWS_PER_WARP 4
#define ROWS_PER_BLOCK (WARPS_PER_BLOCK * ROWS_PER_WARP)   // 32
#define N_BLOCKS (N_ROWS / ROWS_PER_BLOCK)      // 512

// Scratch (no device allocation allowed)
__device__ float g_partials[N_BLOCKS];
__device__ int   g_ticket = 0;

__global__ __launch_bounds__(THREADS_PER_BLOCK)
void fused_loss_kernel(const float* __restrict__ logits,
                       const float* __restrict__ targets,
                       float* __restrict__ out)
{
    __shared__ float s_warp[WARPS_PER_BLOCK];
    __shared__ bool  s_is_last;

    const int lane  = threadIdx.x & 31;
    const int wid   = threadIdx.x >> 5;
    const int row0  = (blockIdx.x * WARPS_PER_BLOCK + wid) * ROWS_PER_WARP;

    // ---- Front-batched loads: 4 rows x (logits,targets), float4 per lane ----
    float4 xv[ROWS_PER_WARP], tv[ROWS_PER_WARP];
#pragma unroll
    for (int r = 0; r < ROWS_PER_WARP; r++) {
        xv[r] = reinterpret_cast<const float4*>(logits  + (size_t)(row0 + r) * V_DIM)[lane];
        tv[r] = reinterpret_cast<const float4*>(targets + (size_t)(row0 + r) * V_DIM)[lane];
    }

    float base  = 0.0f;   // sum of max(x,0) - x*t over all rows
    float hinge = 0.0f;   // sum of hinge over all rows
    float fac[16];        // per-element 1 + exp(-|x|)

#pragma unroll
    for (int r = 0; r < ROWS_PER_WARP; r++) {
        float xs[4] = {xv[r].x, xv[r].y, xv[r].z, xv[r].w};
        float ts[4] = {tv[r].x, tv[r].y, tv[r].z, tv[r].w};

        // ---- BCE pieces: max(x,0) - x*t, and the log factor (1 + e^-|x|) ----
#pragma unroll
        for (int i = 0; i < 4; i++) {
            base += fmaxf(xs[i], 0.0f);
            base  = fmaf(-xs[i], ts[i], base);
            fac[r * 4 + i] = 1.0f + __expf(-fabsf(xs[i]));
        }

        // ---- Hinge via shuffle-broadcast of positives ----
        float c[4];
        bool  p[4];
#pragma unroll
        for (int i = 0; i < 4; i++) {
            p[i] = ts[i] > 0.5f;
            c[i] = p[i] ? -1.0e30f : (1.0f + xs[i]);
        }
#pragma unroll
        for (int i = 0; i < 4; i++) {
            unsigned m = __ballot_sync(0xffffffffu, p[i]);   // warp-uniform
            while (m) {                                      // uniform branch
                int src = __ffs(m) - 1;
                m &= m - 1;
                float pv = __shfl_sync(0xffffffffu, xs[i], src);
                hinge += fmaxf(c[0] - pv, 0.0f);
                hinge += fmaxf(c[1] - pv, 0.0f);
                hinge += fmaxf(c[2] - pv, 0.0f);
                hinge += fmaxf(c[3] - pv, 0.0f);
            }
        }
    }

    // ---- One log per thread: sum log1p(e^-|x|) = log(prod of factors) ----
    // Tree-multiply 16 factors (each in (1,2], product <= 2^16: safe in fp32)
#pragma unroll
    for (int s = 8; s > 0; s >>= 1)
#pragma unroll
        for (int i = 0; i < s; i++)
            fac[i] *= fac[i + s];
    float bce = base + __logf(fac[0]);

    float v = 0.7f * bce + 0.3f * hinge;

    // ---- Warp reduce ----
#pragma unroll
    for (int o = 16; o > 0; o >>= 1)
        v += __shfl_xor_sync(0xffffffffu, v, o);
    if (lane == 0) s_warp[wid] = v;
    __syncthreads();

    // ---- Block reduce (warp 0) + publish + ticket ----
    if (wid == 0) {
        float s = (lane < WARPS_PER_BLOCK) ? s_warp[lane] : 0.0f;
#pragma unroll
        for (int o = 16; o > 0; o >>= 1)
            s += __shfl_xor_sync(0xffffffffu, s, o);
        if (lane == 0) {
            g_partials[blockIdx.x] = s;
            __threadfence();
            int t = atomicAdd(&g_ticket, 1);
            s_is_last = (t == N_BLOCKS - 1);
        }
    }
    __syncthreads();

    // ---- Last block: deterministic reduction of 512 partials ----
    if (s_is_last) {
        __threadfence();
        float s = 0.0f;
#pragma unroll
        for (int i = 0; i < N_BLOCKS / THREADS_PER_BLOCK; i++)
            s += g_partials[threadIdx.x + i * THREADS_PER_BLOCK];
#pragma unroll
        for (int o = 16; o > 0; o >>= 1)
            s += __shfl_xor_sync(0xffffffffu, s, o);
        if (lane == 0) s_warp[wid] = s;
        __syncthreads();
        if (wid == 0) {
            float r2 = (lane < WARPS_PER_BLOCK) ? s_warp[lane] : 0.0f;
#pragma unroll
            for (int o = 16; o > 0; o >>= 1)
                r2 += __shfl_xor_sync(0xffffffffu, r2, o);
            if (lane == 0) {
                out[0] = r2 * (1.0f / ((float)V_DIM * (float)N_ROWS));
                g_ticket = 0;   // reset for graph replay
            }
        }
    }
}

extern "C" void kernel_launch(void* const* d_in, const int* in_sizes, int n_in,
                              void* d_out, int out_size)
{
    const float* logits  = (const float*)d_in[0];
    const float* targets = (const float*)d_in[1];
    float* out = (float*)d_out;

    fused_loss_kernel<<<N_BLOCKS, THREADS_PER_BLOCK>>>(logits, targets, out);
}

// round 6
// speedup vs baseline: 1.0574x; 1.0574x over previous
#include <cuda_runtime.h>
#include <cuda_bf16.h>
#include <cstdint>

#define B_DIM 16
#define T_DIM 1024
#define V_DIM 128
#define N_ROWS (B_DIM * T_DIM)                  // 16384
#define WARPS_PER_BLOCK 4
#define THREADS_PER_BLOCK (WARPS_PER_BLOCK * 32)   // 128
#define ROWS_PER_WARP 2
#define ROWS_PER_BLOCK (WARPS_PER_BLOCK * ROWS_PER_WARP)   // 8
#define N_BLOCKS (N_ROWS / ROWS_PER_BLOCK)      // 2048

// Scratch (no device allocation allowed)
__device__ float g_partials[N_BLOCKS];
__device__ int   g_ticket = 0;

__global__ __launch_bounds__(THREADS_PER_BLOCK)
void fused_loss_kernel(const float* __restrict__ logits,
                       const float* __restrict__ targets,
                       float* __restrict__ out)
{
    __shared__ float s_warp[WARPS_PER_BLOCK];
    __shared__ bool  s_is_last;

    const int lane  = threadIdx.x & 31;
    const int wid   = threadIdx.x >> 5;
    const int row0  = (blockIdx.x * WARPS_PER_BLOCK + wid) * ROWS_PER_WARP;

    // ---- Front-batched loads: 2 rows x (logits,targets), float4 per lane ----
    const float4* xr0 = reinterpret_cast<const float4*>(logits  + (size_t)row0 * V_DIM);
    const float4* tr0 = reinterpret_cast<const float4*>(targets + (size_t)row0 * V_DIM);
    const float4* xr1 = reinterpret_cast<const float4*>(logits  + (size_t)(row0 + 1) * V_DIM);
    const float4* tr1 = reinterpret_cast<const float4*>(targets + (size_t)(row0 + 1) * V_DIM);
    float4 xv0 = xr0[lane];
    float4 tv0 = tr0[lane];
    float4 xv1 = xr1[lane];
    float4 tv1 = tr1[lane];

    float base  = 0.0f;   // sum of max(x,0) - x*t
    float hinge = 0.0f;
    float prod  = 1.0f;   // product of (1 + e^-|x|), 8 factors <= 256: fp32-safe

#pragma unroll
    for (int r = 0; r < ROWS_PER_WARP; r++) {
        float xs[4], ts[4];
        if (r == 0) { xs[0]=xv0.x; xs[1]=xv0.y; xs[2]=xv0.z; xs[3]=xv0.w;
                      ts[0]=tv0.x; ts[1]=tv0.y; ts[2]=tv0.z; ts[3]=tv0.w; }
        else        { xs[0]=xv1.x; xs[1]=xv1.y; xs[2]=xv1.z; xs[3]=xv1.w;
                      ts[0]=tv1.x; ts[1]=tv1.y; ts[2]=tv1.z; ts[3]=tv1.w; }

        // ---- BCE pieces: max(x,0) - x*t accumulated; log factors multiplied ----
#pragma unroll
        for (int i = 0; i < 4; i++) {
            base += fmaxf(xs[i], 0.0f);
            base  = fmaf(-xs[i], ts[i], base);
            prod *= (1.0f + __expf(-fabsf(xs[i])));
        }

        // ---- Hinge via shuffle-broadcast of positives (no smem) ----
        float c[4];
        bool  p[4];
#pragma unroll
        for (int i = 0; i < 4; i++) {
            p[i] = ts[i] > 0.5f;
            c[i] = p[i] ? -1.0e30f : (1.0f + xs[i]);
        }
#pragma unroll
        for (int i = 0; i < 4; i++) {
            unsigned m = __ballot_sync(0xffffffffu, p[i]);   // warp-uniform
            while (m) {                                      // uniform branch
                int src = __ffs(m) - 1;
                m &= m - 1;
                float pv = __shfl_sync(0xffffffffu, xs[i], src);
                hinge += fmaxf(c[0] - pv, 0.0f);
                hinge += fmaxf(c[1] - pv, 0.0f);
                hinge += fmaxf(c[2] - pv, 0.0f);
                hinge += fmaxf(c[3] - pv, 0.0f);
            }
        }
    }

    // One MUFU log per thread replaces 16 log1p(exp(.)) pairs
    float bce = base + __logf(prod);
    float v = 0.7f * bce + 0.3f * hinge;

    // ---- Warp reduce ----
#pragma unroll
    for (int o = 16; o > 0; o >>= 1)
        v += __shfl_xor_sync(0xffffffffu, v, o);
    if (lane == 0) s_warp[wid] = v;
    __syncthreads();

    // ---- Block reduce (warp 0) + publish + ticket ----
    if (wid == 0) {
        float s = (lane < WARPS_PER_BLOCK) ? s_warp[lane] : 0.0f;
#pragma unroll
        for (int o = 16; o > 0; o >>= 1)
            s += __shfl_xor_sync(0xffffffffu, s, o);
        if (lane == 0) {
            g_partials[blockIdx.x] = s;
            __threadfence();
            int t = atomicAdd(&g_ticket, 1);
            s_is_last = (t == N_BLOCKS - 1);
        }
    }
    __syncthreads();

    // ---- Last block: deterministic reduction of 2048 partials ----
    if (s_is_last) {
        __threadfence();
        float s = 0.0f;
#pragma unroll
        for (int i = 0; i < N_BLOCKS / THREADS_PER_BLOCK; i++)   // 16 each
            s += g_partials[threadIdx.x + i * THREADS_PER_BLOCK];
#pragma unroll
        for (int o = 16; o > 0; o >>= 1)
            s += __shfl_xor_sync(0xffffffffu, s, o);
        if (lane == 0) s_warp[wid] = s;
        __syncthreads();
        if (wid == 0) {
            float r2 = (lane < WARPS_PER_BLOCK) ? s_warp[lane] : 0.0f;
#pragma unroll
            for (int o = 16; o > 0; o >>= 1)
                r2 += __shfl_xor_sync(0xffffffffu, r2, o);
            if (lane == 0) {
                out[0] = r2 * (1.0f / ((float)V_DIM * (float)N_ROWS));
                g_ticket = 0;   // reset for graph replay
            }
        }
    }
}

extern "C" void kernel_launch(void* const* d_in, const int* in_sizes, int n_in,
                              void* d_out, int out_size)
{
    const float* logits  = (const float*)d_in[0];
    const float* targets = (const float*)d_in[1];
    float* out = (float*)d_out;

    fused_loss_kernel<<<N_BLOCKS, THREADS_PER_BLOCK>>>(logits, targets, out);
}

// round 7
// speedup vs baseline: 1.0671x; 1.0091x over previous
#include <cuda_runtime.h>
#include <cuda_bf16.h>
#include <cstdint>

#define B_DIM 16
#define T_DIM 1024
#define V_DIM 128
#define N_ROWS (B_DIM * T_DIM)                  // 16384
#define WARPS_PER_BLOCK 4
#define THREADS_PER_BLOCK (WARPS_PER_BLOCK * 32)   // 128
#define ROWS_PER_WARP 4
#define ROWS_PER_BLOCK (WARPS_PER_BLOCK * ROWS_PER_WARP)   // 16
#define N_BLOCKS (N_ROWS / ROWS_PER_BLOCK)      // 1024  -> single wave

// Scratch (no device allocation allowed)
__device__ float g_partials[N_BLOCKS];
__device__ int   g_ticket = 0;

__global__ __launch_bounds__(THREADS_PER_BLOCK)
void fused_loss_kernel(const float* __restrict__ logits,
                       const float* __restrict__ targets,
                       float* __restrict__ out)
{
    __shared__ float s_warp[WARPS_PER_BLOCK];
    __shared__ bool  s_is_last;

    const int lane  = threadIdx.x & 31;
    const int wid   = threadIdx.x >> 5;
    const int row0  = (blockIdx.x * WARPS_PER_BLOCK + wid) * ROWS_PER_WARP;

    // ---- Front-batch ALL loads: 4 rows x (logits,targets), float4 per lane ----
    float4 xv[ROWS_PER_WARP], tv[ROWS_PER_WARP];
#pragma unroll
    for (int r = 0; r < ROWS_PER_WARP; r++) {
        xv[r] = reinterpret_cast<const float4*>(logits  + (size_t)(row0 + r) * V_DIM)[lane];
        tv[r] = reinterpret_cast<const float4*>(targets + (size_t)(row0 + r) * V_DIM)[lane];
    }

    float base  = 0.0f;   // sum of max(x,0) - x*t
    float hinge = 0.0f;
    float prod  = 1.0f;   // product of (1 + e^-|x|): 16 factors <= 2^16, fp32-safe

#pragma unroll
    for (int r = 0; r < ROWS_PER_WARP; r++) {
        float xs[4] = {xv[r].x, xv[r].y, xv[r].z, xv[r].w};
        float ts[4] = {tv[r].x, tv[r].y, tv[r].z, tv[r].w};

        // ---- BCE pieces ----
#pragma unroll
        for (int i = 0; i < 4; i++) {
            base += fmaxf(xs[i], 0.0f);
            base  = fmaf(-xs[i], ts[i], base);
            prod *= (1.0f + __expf(-fabsf(xs[i])));
        }

        // ---- Hinge via shuffle-broadcast of positives ----
        float c[4];
        bool  p[4];
#pragma unroll
        for (int i = 0; i < 4; i++) {
            p[i] = ts[i] > 0.5f;
            c[i] = p[i] ? -1.0e30f : (1.0f + xs[i]);
        }
#pragma unroll
        for (int i = 0; i < 4; i++) {
            unsigned m = __ballot_sync(0xffffffffu, p[i]);   // warp-uniform
            while (m) {                                      // uniform branch
                int src = __ffs(m) - 1;
                m &= m - 1;
                float pv = __shfl_sync(0xffffffffu, xs[i], src);
                hinge += fmaxf(c[0] - pv, 0.0f);
                hinge += fmaxf(c[1] - pv, 0.0f);
                hinge += fmaxf(c[2] - pv, 0.0f);
                hinge += fmaxf(c[3] - pv, 0.0f);
            }
        }
    }

    // One MUFU log per thread
    float bce = base + __logf(prod);
    float v = 0.7f * bce + 0.3f * hinge;

    // ---- Warp reduce ----
#pragma unroll
    for (int o = 16; o > 0; o >>= 1)
        v += __shfl_xor_sync(0xffffffffu, v, o);
    if (lane == 0) s_warp[wid] = v;
    __syncthreads();

    // ---- Block reduce (warp 0) + publish + ticket ----
    if (wid == 0) {
        float s = (lane < WARPS_PER_BLOCK) ? s_warp[lane] : 0.0f;
#pragma unroll
        for (int o = 16; o > 0; o >>= 1)
            s += __shfl_xor_sync(0xffffffffu, s, o);
        if (lane == 0) {
            g_partials[blockIdx.x] = s;
            __threadfence();
            int t = atomicAdd(&g_ticket, 1);
            s_is_last = (t == N_BLOCKS - 1);
        }
    }
    __syncthreads();

    // ---- Last block: deterministic reduction of 1024 partials ----
    if (s_is_last) {
        __threadfence();
        float s = 0.0f;
#pragma unroll
        for (int i = 0; i < N_BLOCKS / THREADS_PER_BLOCK; i++)   // 8 each
            s += g_partials[threadIdx.x + i * THREADS_PER_BLOCK];
#pragma unroll
        for (int o = 16; o > 0; o >>= 1)
            s += __shfl_xor_sync(0xffffffffu, s, o);
        if (lane == 0) s_warp[wid] = s;
        __syncthreads();
        if (wid == 0) {
            float r2 = (lane < WARPS_PER_BLOCK) ? s_warp[lane] : 0.0f;
#pragma unroll
            for (int o = 16; o > 0; o >>= 1)
                r2 += __shfl_xor_sync(0xffffffffu, r2, o);
            if (lane == 0) {
                out[0] = r2 * (1.0f / ((float)V_DIM * (float)N_ROWS));
                g_ticket = 0;   // reset for graph replay
            }
        }
    }
}

extern "C" void kernel_launch(void* const* d_in, const int* in_sizes, int n_in,
                              void* d_out, int out_size)
{
    const float* logits  = (const float*)d_in[0];
    const float* targets = (const float*)d_in[1];
    float* out = (float*)d_out;

    fused_loss_kernel<<<N_BLOCKS, THREADS_PER_BLOCK>>>(logits, targets, out);
}